// round 3
// baseline (speedup 1.0000x reference)
#include <cuda_runtime.h>
#include <cstdint>

#define VM_D         16
#define VM_NINC      1000
#define VM_BLOCK     1024
#define VM_CTAS      148
#define VM_DEPTH     4
#define VM_BUFSTRIDE (VM_BLOCK * 16)              // 16 KB per pipeline stage
#define VM_BUFBYTES  (VM_DEPTH * VM_BUFSTRIDE)    // 64 KB
#define VM_TABLE_BYTES (VM_D * VM_NINC * 8)       // 128 KB (float2 per bin)
#define VM_SMEM_BYTES  (VM_BUFBYTES + VM_TABLE_BYTES)

__global__ __launch_bounds__(VM_BLOCK, 1)
void vegas_map_kernel(const float* __restrict__ y,
                      const float* __restrict__ grid,
                      const float* __restrict__ inc,
                      float* __restrict__ x_out,
                      float* __restrict__ jac_out,
                      int n_f4)
{
    extern __shared__ unsigned char smem_raw[];
    float2* __restrict__ pairs = reinterpret_cast<float2*>(smem_raw + VM_BUFBYTES);

    const int tid    = threadIdx.x;
    const int stride = VM_CTAS * VM_BLOCK;
    const int i0     = blockIdx.x * VM_BLOCK + tid;

    const float4* __restrict__ y4 = reinterpret_cast<const float4*>(y);
    float4* __restrict__       x4 = reinterpret_cast<float4*>(x_out);

    const uint32_t sbuf =
        (uint32_t)__cvta_generic_to_shared(smem_raw) + (uint32_t)tid * 16u;

    // ---- Prologue: launch DEPTH prefetches of this thread's y float4s ----
    #pragma unroll
    for (int k = 0; k < VM_DEPTH; ++k) {
        int idx = i0 + k * stride;
        idx = min(idx, n_f4 - 1);
        asm volatile("cp.async.cg.shared.global [%0], [%1], 16;\n"
                     "cp.async.commit_group;\n"
                     :: "r"(sbuf + (uint32_t)(k * VM_BUFSTRIDE)),
                        "l"(y4 + idx) : "memory");
    }

    // ---- Fill interleaved (grid, inc) table (overlaps with prefetches) ----
    for (int t = tid; t < VM_D * VM_NINC; t += VM_BLOCK) {
        int d = t / VM_NINC;
        int i = t - d * VM_NINC;
        pairs[t] = make_float2(__ldg(grid + d * (VM_NINC + 1) + i),
                               __ldg(inc + d * VM_NINC + i));
    }
    __syncthreads();

    // Thread owns 4 dims: [4q .. 4q+3], quad of threads covers a sample.
    const int q = tid & 3;
    const float2* __restrict__ pb = pairs + q * 4 * VM_NINC;
    const float ninc_f = (float)VM_NINC;

    uint32_t soff = 0;

    for (int i = i0; i < n_f4; i += stride) {
        // Wait for oldest prefetch, read it from smem
        asm volatile("cp.async.wait_group %0;" :: "n"(VM_DEPTH - 1) : "memory");
        float4 yv;
        asm volatile("ld.shared.v4.f32 {%0,%1,%2,%3}, [%4];"
                     : "=f"(yv.x), "=f"(yv.y), "=f"(yv.z), "=f"(yv.w)
                     : "r"(sbuf + soff));

        // Refill the slot we just consumed with data DEPTH strides ahead
        {
            int pidx = i + VM_DEPTH * stride;
            pidx = min(pidx, n_f4 - 1);
            asm volatile("cp.async.cg.shared.global [%0], [%1], 16;\n"
                         "cp.async.commit_group;\n"
                         :: "r"(sbuf + soff), "l"(y4 + pidx) : "memory");
        }
        soff = (soff + VM_BUFSTRIDE) & (VM_BUFBYTES - 1);

        float4 xv;
        float fac;
        {
            float t = yv.x * ninc_f;
            int   iy = min(__float2int_rd(t), VM_NINC - 1);
            float fi = (float)iy;
            float dy = fminf(t - fi, 1.0f);   // y>=1 clamps to right edge (grid=cumsum(inc))
            float2 p = pb[iy];
            xv.x = fmaf(p.y, dy, p.x);
            fac  = p.y * ninc_f;
        }
        {
            float t = yv.y * ninc_f;
            int   iy = min(__float2int_rd(t), VM_NINC - 1);
            float fi = (float)iy;
            float dy = fminf(t - fi, 1.0f);
            float2 p = pb[VM_NINC + iy];
            xv.y = fmaf(p.y, dy, p.x);
            fac *= p.y * ninc_f;
        }
        {
            float t = yv.z * ninc_f;
            int   iy = min(__float2int_rd(t), VM_NINC - 1);
            float fi = (float)iy;
            float dy = fminf(t - fi, 1.0f);
            float2 p = pb[2 * VM_NINC + iy];
            xv.z = fmaf(p.y, dy, p.x);
            fac *= p.y * ninc_f;
        }
        {
            float t = yv.w * ninc_f;
            int   iy = min(__float2int_rd(t), VM_NINC - 1);
            float fi = (float)iy;
            float dy = fminf(t - fi, 1.0f);
            float2 p = pb[3 * VM_NINC + iy];
            xv.w = fmaf(p.y, dy, p.x);
            fac *= p.y * ninc_f;
        }

        x4[i] = xv;

        // Product across the 4 threads of this sample's quad
        fac *= __shfl_xor_sync(0xFFFFFFFFu, fac, 1);
        fac *= __shfl_xor_sync(0xFFFFFFFFu, fac, 2);
        if (q == 0) {
            jac_out[i >> 2] = fac;
        }
    }

    asm volatile("cp.async.wait_group 0;" ::: "memory");
}

extern "C" void kernel_launch(void* const* d_in, const int* in_sizes, int n_in,
                              void* d_out, int out_size)
{
    const float* y    = (const float*)d_in[0];
    const float* grid = (const float*)d_in[1];
    const float* inc  = (const float*)d_in[2];

    const int B = in_sizes[0] / VM_D;               // 1,048,576
    float* x   = (float*)d_out;                     // [B,16]
    float* jac = (float*)d_out + (size_t)B * VM_D;  // [B]

    const int n_f4 = B * (VM_D / 4);                // 4,194,304

    cudaFuncSetAttribute(vegas_map_kernel,
                         cudaFuncAttributeMaxDynamicSharedMemorySize,
                         (int)VM_SMEM_BYTES);

    vegas_map_kernel<<<VM_CTAS, VM_BLOCK, VM_SMEM_BYTES>>>(y, grid, inc, x, jac, n_f4);
}

// round 4
// speedup vs baseline: 4.4912x; 4.4912x over previous
#include <cuda_runtime.h>
#include <cstdint>

#define VM_D        16
#define VM_NINC     1000
#define VM_BLOCK    1024
#define VM_CTAS     148
#define VM_UNROLL   4
#define VM_TABLE_BYTES (VM_D * VM_NINC * 8)   // 128 KB: float2 (grid, inc) per bin

__global__ __launch_bounds__(VM_BLOCK, 1)
void vegas_map_kernel(const float* __restrict__ y,
                      const float* __restrict__ grid,
                      const float* __restrict__ inc,
                      float* __restrict__ x_out,
                      float* __restrict__ jac_out,
                      int n_f4)
{
    extern __shared__ unsigned char smem_raw[];
    float2* __restrict__ pairs = reinterpret_cast<float2*>(smem_raw);

    const int tid = threadIdx.x;

    // ---- Fill interleaved (grid, inc) table into shared memory ----
    for (int t = tid; t < VM_D * VM_NINC; t += VM_BLOCK) {
        int d = t / VM_NINC;
        int i = t - d * VM_NINC;
        pairs[t] = make_float2(__ldg(grid + d * (VM_NINC + 1) + i),
                               __ldg(inc + d * VM_NINC + i));
    }
    __syncthreads();

    // Thread owns 4 dims: [4q .. 4q+3]; a quad of threads covers one sample.
    const int q = tid & 3;
    const float2* __restrict__ pb = pairs + q * 4 * VM_NINC;
    const float ninc_f = (float)VM_NINC;

    const float4* __restrict__ y4 = reinterpret_cast<const float4*>(y);
    float4* __restrict__       x4 = reinterpret_cast<float4*>(x_out);

    const int stride = VM_CTAS * VM_BLOCK;               // 151552
    const int step   = stride * VM_UNROLL;
    const int i0     = blockIdx.x * VM_BLOCK + tid;

    // n_f4 = 4194304, stride = 151552: 27 full strides + remainder.
    // Main loop: batches of VM_UNROLL independent iterations.
    int i = i0;
    for (; i + (VM_UNROLL - 1) * stride < n_f4; i += step) {
        // ---- Front-batched loads: 4 independent LDG.128 in flight ----
        float4 yv[VM_UNROLL];
        #pragma unroll
        for (int u = 0; u < VM_UNROLL; ++u) {
            yv[u] = __ldg(y4 + i + u * stride);
        }

        #pragma unroll
        for (int u = 0; u < VM_UNROLL; ++u) {
            const int ii = i + u * stride;
            float4 xv;
            float fac;
            {
                float t = yv[u].x * ninc_f;
                int   iy = min(__float2int_rd(t), VM_NINC - 1);
                float dy = fminf(t - (float)iy, 1.0f);
                float2 p = pb[iy];
                xv.x = fmaf(p.y, dy, p.x);
                fac  = p.y * ninc_f;
            }
            {
                float t = yv[u].y * ninc_f;
                int   iy = min(__float2int_rd(t), VM_NINC - 1);
                float dy = fminf(t - (float)iy, 1.0f);
                float2 p = pb[VM_NINC + iy];
                xv.y = fmaf(p.y, dy, p.x);
                fac *= p.y * ninc_f;
            }
            {
                float t = yv[u].z * ninc_f;
                int   iy = min(__float2int_rd(t), VM_NINC - 1);
                float dy = fminf(t - (float)iy, 1.0f);
                float2 p = pb[2 * VM_NINC + iy];
                xv.z = fmaf(p.y, dy, p.x);
                fac *= p.y * ninc_f;
            }
            {
                float t = yv[u].w * ninc_f;
                int   iy = min(__float2int_rd(t), VM_NINC - 1);
                float dy = fminf(t - (float)iy, 1.0f);
                float2 p = pb[3 * VM_NINC + iy];
                xv.w = fmaf(p.y, dy, p.x);
                fac *= p.y * ninc_f;
            }

            x4[ii] = xv;

            fac *= __shfl_xor_sync(0xFFFFFFFFu, fac, 1);
            fac *= __shfl_xor_sync(0xFFFFFFFFu, fac, 2);
            if (q == 0) {
                jac_out[ii >> 2] = fac;
            }
        }
    }

    // ---- Remainder ----
    for (; i < n_f4; i += stride) {
        const float4 yv = __ldg(y4 + i);
        float4 xv;
        float fac;
        {
            float t = yv.x * ninc_f;
            int   iy = min(__float2int_rd(t), VM_NINC - 1);
            float dy = fminf(t - (float)iy, 1.0f);
            float2 p = pb[iy];
            xv.x = fmaf(p.y, dy, p.x);
            fac  = p.y * ninc_f;
        }
        {
            float t = yv.y * ninc_f;
            int   iy = min(__float2int_rd(t), VM_NINC - 1);
            float dy = fminf(t - (float)iy, 1.0f);
            float2 p = pb[VM_NINC + iy];
            xv.y = fmaf(p.y, dy, p.x);
            fac *= p.y * ninc_f;
        }
        {
            float t = yv.z * ninc_f;
            int   iy = min(__float2int_rd(t), VM_NINC - 1);
            float dy = fminf(t - (float)iy, 1.0f);
            float2 p = pb[2 * VM_NINC + iy];
            xv.z = fmaf(p.y, dy, p.x);
            fac *= p.y * ninc_f;
        }
        {
            float t = yv.w * ninc_f;
            int   iy = min(__float2int_rd(t), VM_NINC - 1);
            float dy = fminf(t - (float)iy, 1.0f);
            float2 p = pb[3 * VM_NINC + iy];
            xv.w = fmaf(p.y, dy, p.x);
            fac *= p.y * ninc_f;
        }

        x4[i] = xv;

        fac *= __shfl_xor_sync(0xFFFFFFFFu, fac, 1);
        fac *= __shfl_xor_sync(0xFFFFFFFFu, fac, 2);
        if (q == 0) {
            jac_out[i >> 2] = fac;
        }
    }
}

extern "C" void kernel_launch(void* const* d_in, const int* in_sizes, int n_in,
                              void* d_out, int out_size)
{
    const float* y    = (const float*)d_in[0];
    const float* grid = (const float*)d_in[1];
    const float* inc  = (const float*)d_in[2];

    const int B = in_sizes[0] / VM_D;               // 1,048,576
    float* x   = (float*)d_out;                     // [B,16]
    float* jac = (float*)d_out + (size_t)B * VM_D;  // [B]

    const int n_f4 = B * (VM_D / 4);                // 4,194,304

    cudaFuncSetAttribute(vegas_map_kernel,
                         cudaFuncAttributeMaxDynamicSharedMemorySize,
                         (int)VM_TABLE_BYTES);

    vegas_map_kernel<<<VM_CTAS, VM_BLOCK, VM_TABLE_BYTES>>>(y, grid, inc, x, jac, n_f4);
}

// round 5
// speedup vs baseline: 5.2903x; 1.1779x over previous
#include <cuda_runtime.h>
#include <cstdint>

#define VM_D        16
#define VM_NINC     1000
#define VM_BLOCK    768
#define VM_CTAS     148
#define VM_UNROLL   4
#define VM_TABLE_BYTES (VM_D * VM_NINC * 8)   // 128 KB: float2 (grid, inc) per bin

__device__ __forceinline__ void vm_process(const float4 yv,
                                           const float2* __restrict__ pb,
                                           float4& xv, float& fac)
{
    const float ninc_f = (float)VM_NINC;
    {
        float t = yv.x * ninc_f;
        int   iy = min(__float2int_rd(t), VM_NINC - 1);
        float dy = fminf(t - (float)iy, 1.0f);
        float2 p = pb[iy];
        xv.x = fmaf(p.y, dy, p.x);
        fac  = p.y * ninc_f;
    }
    {
        float t = yv.y * ninc_f;
        int   iy = min(__float2int_rd(t), VM_NINC - 1);
        float dy = fminf(t - (float)iy, 1.0f);
        float2 p = pb[VM_NINC + iy];
        xv.y = fmaf(p.y, dy, p.x);
        fac *= p.y * ninc_f;
    }
    {
        float t = yv.z * ninc_f;
        int   iy = min(__float2int_rd(t), VM_NINC - 1);
        float dy = fminf(t - (float)iy, 1.0f);
        float2 p = pb[2 * VM_NINC + iy];
        xv.z = fmaf(p.y, dy, p.x);
        fac *= p.y * ninc_f;
    }
    {
        float t = yv.w * ninc_f;
        int   iy = min(__float2int_rd(t), VM_NINC - 1);
        float dy = fminf(t - (float)iy, 1.0f);
        float2 p = pb[3 * VM_NINC + iy];
        xv.w = fmaf(p.y, dy, p.x);
        fac *= p.y * ninc_f;
    }
}

__global__ __launch_bounds__(VM_BLOCK, 1)
void vegas_map_kernel(const float* __restrict__ y,
                      const float* __restrict__ grid,
                      const float* __restrict__ inc,
                      float* __restrict__ x_out,
                      float* __restrict__ jac_out,
                      int n_f4)
{
    extern __shared__ unsigned char smem_raw[];
    float2* __restrict__ pairs = reinterpret_cast<float2*>(smem_raw);

    const int tid = threadIdx.x;

    // ---- Fill interleaved (grid, inc) table into shared memory ----
    for (int t = tid; t < VM_D * VM_NINC; t += VM_BLOCK) {
        int d = t / VM_NINC;
        int i = t - d * VM_NINC;
        pairs[t] = make_float2(__ldg(grid + d * (VM_NINC + 1) + i),
                               __ldg(inc + d * VM_NINC + i));
    }
    __syncthreads();

    // Thread owns 4 dims [4q..4q+3]; quad of threads covers one sample.
    const int q = tid & 3;
    const float2* __restrict__ pb = pairs + q * 4 * VM_NINC;

    const float4* __restrict__ y4 = reinterpret_cast<const float4*>(y);
    float4* __restrict__       x4 = reinterpret_cast<float4*>(x_out);

    const int stride = VM_CTAS * VM_BLOCK;      // 113664
    const int step   = stride * VM_UNROLL;
    const int i0     = blockIdx.x * VM_BLOCK + tid;

    int i = i0;
    bool have = (i + (VM_UNROLL - 1) * stride < n_f4);

    float4 cur[VM_UNROLL];
    if (have) {
        #pragma unroll
        for (int u = 0; u < VM_UNROLL; ++u) cur[u] = __ldg(y4 + i + u * stride);
    }

    // ---- Software-pipelined main loop: prefetch batch k+1 before processing batch k ----
    while (have) {
        const int inext = i + step;
        const bool have_next = (inext + (VM_UNROLL - 1) * stride < n_f4);

        float4 nxt[VM_UNROLL];
        if (have_next) {
            #pragma unroll
            for (int u = 0; u < VM_UNROLL; ++u) nxt[u] = __ldg(y4 + inext + u * stride);
        }

        #pragma unroll
        for (int u = 0; u < VM_UNROLL; ++u) {
            const int ii = i + u * stride;
            float4 xv;
            float fac;
            vm_process(cur[u], pb, xv, fac);

            x4[ii] = xv;

            fac *= __shfl_xor_sync(0xFFFFFFFFu, fac, 1);
            fac *= __shfl_xor_sync(0xFFFFFFFFu, fac, 2);
            if (q == 0) {
                jac_out[ii >> 2] = fac;
            }
        }

        #pragma unroll
        for (int u = 0; u < VM_UNROLL; ++u) cur[u] = nxt[u];
        i = inext;
        have = have_next;
    }

    // ---- Remainder: single-iteration strided loop ----
    for (; i < n_f4; i += stride) {
        const float4 yv = __ldg(y4 + i);
        float4 xv;
        float fac;
        vm_process(yv, pb, xv, fac);

        x4[i] = xv;

        fac *= __shfl_xor_sync(0xFFFFFFFFu, fac, 1);
        fac *= __shfl_xor_sync(0xFFFFFFFFu, fac, 2);
        if (q == 0) {
            jac_out[i >> 2] = fac;
        }
    }
}

extern "C" void kernel_launch(void* const* d_in, const int* in_sizes, int n_in,
                              void* d_out, int out_size)
{
    const float* y    = (const float*)d_in[0];
    const float* grid = (const float*)d_in[1];
    const float* inc  = (const float*)d_in[2];

    const int B = in_sizes[0] / VM_D;               // 1,048,576
    float* x   = (float*)d_out;                     // [B,16]
    float* jac = (float*)d_out + (size_t)B * VM_D;  // [B]

    const int n_f4 = B * (VM_D / 4);                // 4,194,304

    cudaFuncSetAttribute(vegas_map_kernel,
                         cudaFuncAttributeMaxDynamicSharedMemorySize,
                         (int)VM_TABLE_BYTES);

    vegas_map_kernel<<<VM_CTAS, VM_BLOCK, VM_TABLE_BYTES>>>(y, grid, inc, x, jac, n_f4);
}

// round 6
// speedup vs baseline: 5.2958x; 1.0010x over previous
#include <cuda_runtime.h>
#include <cstdint>

#define VM_D        16
#define VM_NINC     1000
#define VM_BLOCK    768
#define VM_CTAS     148
#define VM_UNROLL   4
#define VM_TABLE_BYTES (VM_D * VM_NINC * 8)   // 128 KB: float2 (grid, inc) per bin

__device__ __forceinline__ void vm_process(const float4 yv,
                                           const float2* __restrict__ pb,
                                           float4& xv, float& fac)
{
    const float ninc_f = (float)VM_NINC;
    // y in [0,1): iy = floor(y*1000) <= 999 always (max fp32 y*1000 = 999.99994).
    // min() kept only as an OOB-safety guard; dy in [0,1) by construction.
    {
        float t = yv.x * ninc_f;
        int   iy = min(__float2int_rd(t), VM_NINC - 1);
        float dy = t - (float)iy;
        float2 p = pb[iy];
        xv.x = fmaf(p.y, dy, p.x);
        fac  = p.y * ninc_f;
    }
    {
        float t = yv.y * ninc_f;
        int   iy = min(__float2int_rd(t), VM_NINC - 1);
        float dy = t - (float)iy;
        float2 p = pb[VM_NINC + iy];
        xv.y = fmaf(p.y, dy, p.x);
        fac *= p.y * ninc_f;
    }
    {
        float t = yv.z * ninc_f;
        int   iy = min(__float2int_rd(t), VM_NINC - 1);
        float dy = t - (float)iy;
        float2 p = pb[2 * VM_NINC + iy];
        xv.z = fmaf(p.y, dy, p.x);
        fac *= p.y * ninc_f;
    }
    {
        float t = yv.w * ninc_f;
        int   iy = min(__float2int_rd(t), VM_NINC - 1);
        float dy = t - (float)iy;
        float2 p = pb[3 * VM_NINC + iy];
        xv.w = fmaf(p.y, dy, p.x);
        fac *= p.y * ninc_f;
    }
}

__global__ __launch_bounds__(VM_BLOCK, 1)
void vegas_map_kernel(const float* __restrict__ y,
                      const float* __restrict__ grid,
                      const float* __restrict__ inc,
                      float* __restrict__ x_out,
                      float* __restrict__ jac_out,
                      int n_f4)
{
    extern __shared__ unsigned char smem_raw[];
    float2* __restrict__ pairs = reinterpret_cast<float2*>(smem_raw);

    const int tid = threadIdx.x;

    // ---- Fill interleaved (grid, inc) table into shared memory ----
    for (int t = tid; t < VM_D * VM_NINC; t += VM_BLOCK) {
        int d = t / VM_NINC;
        int i = t - d * VM_NINC;
        pairs[t] = make_float2(__ldg(grid + d * (VM_NINC + 1) + i),
                               __ldg(inc + d * VM_NINC + i));
    }
    __syncthreads();

    // Thread owns 4 dims [4q..4q+3]; quad of threads covers one sample.
    const int q = tid & 3;
    const float2* __restrict__ pb = pairs + q * 4 * VM_NINC;

    const float4* __restrict__ y4 = reinterpret_cast<const float4*>(y);
    float4* __restrict__       x4 = reinterpret_cast<float4*>(x_out);

    const int stride  = VM_CTAS * VM_BLOCK;      // 113664
    const int step    = stride * VM_UNROLL;
    const int i0      = blockIdx.x * VM_BLOCK + tid;
    const int jstride = stride >> 2;             // jac index stride per u-slot

    int i = i0;
    int j = i0 >> 2;                             // jac index of quad 0 slot
    bool have = (i + (VM_UNROLL - 1) * stride < n_f4);

    float4 cur[VM_UNROLL];
    if (have) {
        #pragma unroll
        for (int u = 0; u < VM_UNROLL; ++u) cur[u] = __ldg(y4 + i + u * stride);
    }

    // ---- Software-pipelined main loop: prefetch batch k+1 before processing batch k ----
    while (have) {
        const int inext = i + step;
        const bool have_next = (inext + (VM_UNROLL - 1) * stride < n_f4);

        float4 nxt[VM_UNROLL];
        if (have_next) {
            #pragma unroll
            for (int u = 0; u < VM_UNROLL; ++u) nxt[u] = __ldg(y4 + inext + u * stride);
        }

        #pragma unroll
        for (int u = 0; u < VM_UNROLL; ++u) {
            float4 xv;
            float fac;
            vm_process(cur[u], pb, xv, fac);

            x4[i + u * stride] = xv;

            fac *= __shfl_xor_sync(0xFFFFFFFFu, fac, 1);
            fac *= __shfl_xor_sync(0xFFFFFFFFu, fac, 2);
            if (q == 0) {
                jac_out[j + u * jstride] = fac;
            }
        }

        #pragma unroll
        for (int u = 0; u < VM_UNROLL; ++u) cur[u] = nxt[u];
        i = inext;
        j += step >> 2;
        have = have_next;
    }

    // ---- Remainder: single-iteration strided loop ----
    for (; i < n_f4; i += stride) {
        const float4 yv = __ldg(y4 + i);
        float4 xv;
        float fac;
        vm_process(yv, pb, xv, fac);

        x4[i] = xv;

        fac *= __shfl_xor_sync(0xFFFFFFFFu, fac, 1);
        fac *= __shfl_xor_sync(0xFFFFFFFFu, fac, 2);
        if (q == 0) {
            jac_out[i >> 2] = fac;
        }
    }
}

extern "C" void kernel_launch(void* const* d_in, const int* in_sizes, int n_in,
                              void* d_out, int out_size)
{
    const float* y    = (const float*)d_in[0];
    const float* grid = (const float*)d_in[1];
    const float* inc  = (const float*)d_in[2];

    const int B = in_sizes[0] / VM_D;               // 1,048,576
    float* x   = (float*)d_out;                     // [B,16]
    float* jac = (float*)d_out + (size_t)B * VM_D;  // [B]

    const int n_f4 = B * (VM_D / 4);                // 4,194,304

    cudaFuncSetAttribute(vegas_map_kernel,
                         cudaFuncAttributeMaxDynamicSharedMemorySize,
                         (int)VM_TABLE_BYTES);

    vegas_map_kernel<<<VM_CTAS, VM_BLOCK, VM_TABLE_BYTES>>>(y, grid, inc, x, jac, n_f4);
}